// round 5
// baseline (speedup 1.0000x reference)
#include <cuda_runtime.h>
#include <cstdint>

#define NNODES 50000
#define DFEAT 128

// ---- scratch (device globals: no allocation allowed) ----
__device__ __align__(256) float  g_H[NNODES * DFEAT];   // h = (1+eps)*x + agg
__device__ __align__(256) float  g_Z1[NNODES * DFEAT];  // pre-BN output of linear1
__device__ __align__(256) double g_stats[512];          // sum1,sq1,sum2,sq2 (128 each)
__device__ __align__(256) float  g_bn[512];             // scale1,shift1 ; scale2,shift2
__device__ int g_is64;                                  // edge_index dtype flag

__device__ __forceinline__ uint32_t to_tf32(float x) {
    uint32_t r;
    asm("cvt.rna.tf32.f32 %0, %1;" : "=r"(r) : "f"(x));
    return r;
}

// ============================ small kernels ============================

// zero stats + probe edge dtype. One block, 512 threads.
__global__ void prep_kernel(const void* eiv, int E, int N) {
    int t = threadIdx.x;
    g_stats[t] = 0.0;
    __shared__ int bad;
    if (t == 0) bad = 0;
    __syncthreads();
    const long long* p = (const long long*)eiv;
    int n = E < 1024 ? E : 1024;
    for (int i = t; i < n; i += blockDim.x) {
        long long v = p[i];
        if (v < 0 || v >= (long long)N) atomicOr(&bad, 1);
    }
    __syncthreads();
    if (t == 0) g_is64 = bad ? 0 : 1;
}

// h = (1+eps) * x
__global__ void init_h_kernel(const float* __restrict__ x, const float* __restrict__ eps, int n4) {
    int idx = blockIdx.x * blockDim.x + threadIdx.x;
    if (idx >= n4) return;
    float c = 1.0f + *eps;
    float4 v = ((const float4*)x)[idx];
    v.x *= c; v.y *= c; v.z *= c; v.w *= c;
    ((float4*)g_H)[idx] = v;
}

// edge scatter-add: 8 edges per warp (MLP=8), vector L2 reductions
__global__ void __launch_bounds__(256) scatter_kernel(const float* __restrict__ x,
                                                      const void* __restrict__ eiv, int E) {
    int lane = threadIdx.x & 31;
    int warp = (blockIdx.x * blockDim.x + threadIdx.x) >> 5;
    int e0 = warp * 8;
    if (e0 >= E) return;
    int is64 = g_is64;

    if (e0 + 8 <= E) {
        long long s[8], d[8];
        if (is64) {
            const long long* ei = (const long long*)eiv;
#pragma unroll
            for (int k = 0; k < 8; k++) { s[k] = __ldg(&ei[e0 + k]); d[k] = __ldg(&ei[E + e0 + k]); }
        } else {
            const int* ei = (const int*)eiv;
#pragma unroll
            for (int k = 0; k < 8; k++) { s[k] = __ldg(&ei[e0 + k]); d[k] = __ldg(&ei[E + e0 + k]); }
        }
        float4 v[8];
#pragma unroll
        for (int k = 0; k < 8; k++)
            v[k] = __ldg(((const float4*)(x + s[k] * 128)) + lane);
#pragma unroll
        for (int k = 0; k < 8; k++) {
            float* dp = g_H + d[k] * 128 + (lane << 2);
            asm volatile("red.global.add.v4.f32 [%0], {%1,%2,%3,%4};"
                         :: "l"(dp), "f"(v[k].x), "f"(v[k].y), "f"(v[k].z), "f"(v[k].w) : "memory");
        }
    } else {
        for (int e = e0; e < E; e++) {
            long long s, d;
            if (is64) {
                const long long* ei = (const long long*)eiv;
                s = __ldg(&ei[e]); d = __ldg(&ei[E + e]);
            } else {
                const int* ei = (const int*)eiv;
                s = __ldg(&ei[e]); d = __ldg(&ei[E + e]);
            }
            float4 v = __ldg(((const float4*)(x + s * 128)) + lane);
            float* dp = g_H + d * 128 + (lane << 2);
            asm volatile("red.global.add.v4.f32 [%0], {%1,%2,%3,%4};"
                         :: "l"(dp), "f"(v.x), "f"(v.y), "f"(v.z), "f"(v.w) : "memory");
        }
    }
}

// ============================ tf32 mma.sync GEMM ============================
// Z[m][n] = bias[n] + sum_k f(A[m][k]) * W[n][k]
// MODE 0: A=g_H,  f=identity,             Z=g_Z1
// MODE 1: A=g_Z1, f=relu(bn1(.)) (fused), Z=Zout
// Block: 128x128 tile, K=128 in smem (stride 132, conflict-free frags).
// 256 threads = 8 warps in 4(m) x 2(n); warp tile 32x64; mma.m16n8k8.tf32.
// Column sum/sumsq fused in epilogue.
#define MMA_SMEM_FLOATS (640 + 2 * 128 * 132)
#define MMA_SMEM_BYTES  (MMA_SMEM_FLOATS * 4)

__device__ __forceinline__ void mma_tf32_16n8k8(float c[4], const uint32_t a[4],
                                                uint32_t b0, uint32_t b1) {
    asm volatile(
        "mma.sync.aligned.m16n8k8.row.col.f32.tf32.tf32.f32 "
        "{%0,%1,%2,%3}, {%4,%5,%6,%7}, {%8,%9}, {%0,%1,%2,%3};"
        : "+f"(c[0]), "+f"(c[1]), "+f"(c[2]), "+f"(c[3])
        : "r"(a[0]), "r"(a[1]), "r"(a[2]), "r"(a[3]), "r"(b0), "r"(b1));
}

template <int MODE>
__global__ void __launch_bounds__(256) mma_gemm(const float* __restrict__ Wmat,
                                                const float* __restrict__ bias,
                                                float* __restrict__ Zout, int M) {
    extern __shared__ float sm[];
    float* s_bias  = sm;
    float* s_scale = sm + 128;
    float* s_shift = sm + 256;
    float* s_sum   = sm + 384;
    float* s_sq    = sm + 512;
    float* As      = sm + 640;             // [128][132] (tf32 bits)
    float* Bs      = As + 128 * 132;       // [128][132] (tf32 bits), [n][k]
    const uint32_t* As32 = (const uint32_t*)As;
    const uint32_t* Bs32 = (const uint32_t*)Bs;

    const float* A = MODE ? g_Z1 : g_H;
    float* Z       = MODE ? Zout : g_Z1;

    int tid = threadIdx.x;
    int m0 = blockIdx.x * 128;

    if (tid < 128) {
        s_bias[tid] = bias[tid];
        s_sum[tid] = 0.f;
        s_sq[tid]  = 0.f;
        if (MODE) { s_scale[tid] = g_bn[tid]; s_shift[tid] = g_bn[128 + tid]; }
    }
    __syncthreads();

    // load B (=W, [n][k] natural layout), tf32-rounded
#pragma unroll
    for (int i = 0; i < 16; i++) {
        int idx = i * 256 + tid;          // float4 index, 4096 total
        int n = idx >> 5, k4 = idx & 31;
        float4 v = __ldg(((const float4*)Wmat) + idx);
        uint32_t* dst = (uint32_t*)(Bs + n * 132 + k4 * 4);
        dst[0] = to_tf32(v.x); dst[1] = to_tf32(v.y);
        dst[2] = to_tf32(v.z); dst[3] = to_tf32(v.w);
    }
    // load A tile (fused bn1+relu in MODE 1), tf32-rounded
#pragma unroll
    for (int i = 0; i < 16; i++) {
        int idx = i * 256 + tid;
        int m = idx >> 5, k4 = idx & 31;
        int gm = m0 + m;
        float4 v = make_float4(0.f, 0.f, 0.f, 0.f);
        if (gm < M) v = __ldg(((const float4*)A) + (size_t)gm * 32 + k4);
        if (MODE) {
            int k = k4 * 4;
            v.x = fmaxf(fmaf(v.x, s_scale[k + 0], s_shift[k + 0]), 0.f);
            v.y = fmaxf(fmaf(v.y, s_scale[k + 1], s_shift[k + 1]), 0.f);
            v.z = fmaxf(fmaf(v.z, s_scale[k + 2], s_shift[k + 2]), 0.f);
            v.w = fmaxf(fmaf(v.w, s_scale[k + 3], s_shift[k + 3]), 0.f);
        }
        uint32_t* dst = (uint32_t*)(As + m * 132 + k4 * 4);
        dst[0] = to_tf32(v.x); dst[1] = to_tf32(v.y);
        dst[2] = to_tf32(v.z); dst[3] = to_tf32(v.w);
    }
    __syncthreads();

    int lane = tid & 31;
    int wid  = tid >> 5;
    int g = lane >> 2, t = lane & 3;
    int wm = wid >> 1;                // 0..3
    int wn = wid & 1;                 // 0..1
    int arow = wm * 32;               // warp's A row base (in tile)
    int bcol = wn * 64;               // warp's B col base (in tile)

    float acc[2][8][4];
#pragma unroll
    for (int mt = 0; mt < 2; mt++)
#pragma unroll
        for (int nt = 0; nt < 8; nt++)
#pragma unroll
            for (int q = 0; q < 4; q++) acc[mt][nt][q] = 0.f;

#pragma unroll
    for (int ks = 0; ks < 16; ks++) {
        int k0 = ks * 8;
        uint32_t a[2][4];
#pragma unroll
        for (int mt = 0; mt < 2; mt++) {
            int rb = arow + mt * 16;
            a[mt][0] = As32[(rb + g) * 132 + k0 + t];
            a[mt][1] = As32[(rb + g + 8) * 132 + k0 + t];
            a[mt][2] = As32[(rb + g) * 132 + k0 + t + 4];
            a[mt][3] = As32[(rb + g + 8) * 132 + k0 + t + 4];
        }
#pragma unroll
        for (int nt = 0; nt < 8; nt++) {
            uint32_t b0 = Bs32[(bcol + nt * 8 + g) * 132 + k0 + t];
            uint32_t b1 = Bs32[(bcol + nt * 8 + g) * 132 + k0 + t + 4];
            mma_tf32_16n8k8(acc[0][nt], a[0], b0, b1);
            mma_tf32_16n8k8(acc[1][nt], a[1], b0, b1);
        }
    }

    // epilogue: bias add, store float2 pairs, fused column stats
#pragma unroll
    for (int nt = 0; nt < 8; nt++) {
        int col = bcol + nt * 8 + 2 * t;
        float bi0 = s_bias[col], bi1 = s_bias[col + 1];
        float cs0 = 0.f, cq0 = 0.f, cs1 = 0.f, cq1 = 0.f;
#pragma unroll
        for (int mt = 0; mt < 2; mt++) {
#pragma unroll
            for (int rr = 0; rr < 2; rr++) {
                int gm = m0 + arow + mt * 16 + g + rr * 8;
                if (gm < M) {
                    float o0 = acc[mt][nt][rr * 2 + 0] + bi0;
                    float o1 = acc[mt][nt][rr * 2 + 1] + bi1;
                    float2 ov = make_float2(o0, o1);
                    *(float2*)(Z + (size_t)gm * 128 + col) = ov;
                    cs0 += o0; cq0 += o0 * o0;
                    cs1 += o1; cq1 += o1 * o1;
                }
            }
        }
        atomicAdd(&s_sum[col], cs0);     atomicAdd(&s_sq[col], cq0);
        atomicAdd(&s_sum[col + 1], cs1); atomicAdd(&s_sq[col + 1], cq1);
    }
    __syncthreads();
    if (tid < 128) {
        double* sum = g_stats + (MODE ? 256 : 0);
        double* sq  = g_stats + (MODE ? 384 : 128);
        atomicAdd(&sum[tid], (double)s_sum[tid]);
        atomicAdd(&sq[tid],  (double)s_sq[tid]);
    }
}

// ---- fold BN (mean/var/gamma/beta) into per-column scale/shift ----
template <int MODE>
__global__ void finalize_bn(const float* __restrict__ gamma,
                            const float* __restrict__ beta, int M) {
    int c = threadIdx.x;
    const double* sum = g_stats + (MODE ? 256 : 0);
    const double* sq  = g_stats + (MODE ? 384 : 128);
    double mean = sum[c] / (double)M;
    double var  = sq[c] / (double)M - mean * mean;
    float sc = gamma[c] * rsqrtf((float)var + 1e-5f);
    g_bn[MODE * 256 + c]       = sc;
    g_bn[MODE * 256 + 128 + c] = beta[c] - (float)mean * sc;
}

// ---- final: out = relu(bn2(out)) in place ----
__global__ void bn_relu_out_kernel(float* __restrict__ out, int n4) {
    int idx = blockIdx.x * blockDim.x + threadIdx.x;
    if (idx >= n4) return;
    float4 v = ((float4*)out)[idx];
    int k = (idx & 31) * 4;
    v.x = fmaxf(fmaf(v.x, g_bn[256 + k + 0], g_bn[384 + k + 0]), 0.f);
    v.y = fmaxf(fmaf(v.y, g_bn[256 + k + 1], g_bn[384 + k + 1]), 0.f);
    v.z = fmaxf(fmaf(v.z, g_bn[256 + k + 2], g_bn[384 + k + 2]), 0.f);
    v.w = fmaxf(fmaf(v.w, g_bn[256 + k + 3], g_bn[384 + k + 3]), 0.f);
    ((float4*)out)[idx] = v;
}

extern "C" void kernel_launch(void* const* d_in, const int* in_sizes, int n_in,
                              void* d_out, int out_size) {
    const float* x   = (const float*)d_in[0];
    const void*  ei  = d_in[1];
    // d_in[2] = batch (unused; single graph, BN over all nodes)
    const float* eps = (const float*)d_in[3];
    const float* W1  = (const float*)d_in[4];
    const float* b1  = (const float*)d_in[5];
    const float* g1  = (const float*)d_in[6];
    const float* be1 = (const float*)d_in[7];
    const float* W2  = (const float*)d_in[8];
    const float* b2  = (const float*)d_in[9];
    const float* g2  = (const float*)d_in[10];
    const float* be2 = (const float*)d_in[11];
    float* out = (float*)d_out;

    int N = in_sizes[0] / 128;
    int E = in_sizes[1] / 2;
    int n4 = N * 32;

    cudaFuncSetAttribute(mma_gemm<0>, cudaFuncAttributeMaxDynamicSharedMemorySize, MMA_SMEM_BYTES);
    cudaFuncSetAttribute(mma_gemm<1>, cudaFuncAttributeMaxDynamicSharedMemorySize, MMA_SMEM_BYTES);

    prep_kernel<<<1, 512>>>(ei, E, N);
    init_h_kernel<<<(n4 + 255) / 256, 256>>>(x, eps, n4);
    // 8 edges per warp -> 64 edges per 256-thread block
    scatter_kernel<<<(E + 63) / 64, 256>>>(x, ei, E);

    int gblocks = (N + 127) / 128;
    mma_gemm<0><<<gblocks, 256, MMA_SMEM_BYTES>>>(W1, b1, nullptr, N);
    finalize_bn<0><<<1, 128>>>(g1, be1, N);

    mma_gemm<1><<<gblocks, 256, MMA_SMEM_BYTES>>>(W2, b2, out, N);
    finalize_bn<1><<<1, 128>>>(g2, be2, N);

    bn_relu_out_kernel<<<(n4 + 255) / 256, 256>>>(out, n4);
}

// round 6
// speedup vs baseline: 1.2465x; 1.2465x over previous
#include <cuda_runtime.h>
#include <cstdint>

#define NNODES 50000
#define DFEAT 128

// ---- scratch (device globals: no allocation allowed) ----
__device__ __align__(256) float  g_H[NNODES * DFEAT];   // h = (1+eps)*x + agg
__device__ __align__(256) float  g_Z1[NNODES * DFEAT];  // pre-BN output of linear1
__device__ __align__(256) double g_stats[512];          // sum1,sq1,sum2,sq2 (128 each)
__device__ __align__(256) float  g_bn[512];             // scale1,shift1 ; scale2,shift2
__device__ int g_is64;                                  // edge_index dtype flag

__device__ __forceinline__ uint32_t to_tf32(float x) {
    uint32_t r;
    asm("cvt.rna.tf32.f32 %0, %1;" : "=r"(r) : "f"(x));
    return r;
}

// ============================ small kernels ============================

// zero stats + probe edge dtype. One block, 512 threads.
__global__ void prep_kernel(const void* eiv, int E, int N) {
    int t = threadIdx.x;
    g_stats[t] = 0.0;
    __shared__ int bad;
    if (t == 0) bad = 0;
    __syncthreads();
    const long long* p = (const long long*)eiv;
    int n = E < 1024 ? E : 1024;
    for (int i = t; i < n; i += blockDim.x) {
        long long v = p[i];
        if (v < 0 || v >= (long long)N) atomicOr(&bad, 1);
    }
    __syncthreads();
    if (t == 0) g_is64 = bad ? 0 : 1;
}

// h = (1+eps) * x
__global__ void init_h_kernel(const float* __restrict__ x, const float* __restrict__ eps, int n4) {
    int idx = blockIdx.x * blockDim.x + threadIdx.x;
    if (idx >= n4) return;
    float c = 1.0f + *eps;
    float4 v = ((const float4*)x)[idx];
    v.x *= c; v.y *= c; v.z *= c; v.w *= c;
    ((float4*)g_H)[idx] = v;
}

// edge scatter-add: 8 edges per warp (MLP=8), vector L2 reductions
__global__ void __launch_bounds__(256) scatter_kernel(const float* __restrict__ x,
                                                      const void* __restrict__ eiv, int E) {
    int lane = threadIdx.x & 31;
    int warp = (blockIdx.x * blockDim.x + threadIdx.x) >> 5;
    int e0 = warp * 8;
    if (e0 >= E) return;
    int is64 = g_is64;

    if (e0 + 8 <= E) {
        long long s[8], d[8];
        if (is64) {
            const long long* ei = (const long long*)eiv;
#pragma unroll
            for (int k = 0; k < 8; k++) { s[k] = __ldg(&ei[e0 + k]); d[k] = __ldg(&ei[E + e0 + k]); }
        } else {
            const int* ei = (const int*)eiv;
#pragma unroll
            for (int k = 0; k < 8; k++) { s[k] = __ldg(&ei[e0 + k]); d[k] = __ldg(&ei[E + e0 + k]); }
        }
        float4 v[8];
#pragma unroll
        for (int k = 0; k < 8; k++)
            v[k] = __ldg(((const float4*)(x + s[k] * 128)) + lane);
#pragma unroll
        for (int k = 0; k < 8; k++) {
            float* dp = g_H + d[k] * 128 + (lane << 2);
            asm volatile("red.global.add.v4.f32 [%0], {%1,%2,%3,%4};"
                         :: "l"(dp), "f"(v[k].x), "f"(v[k].y), "f"(v[k].z), "f"(v[k].w) : "memory");
        }
    } else {
        for (int e = e0; e < E; e++) {
            long long s, d;
            if (is64) {
                const long long* ei = (const long long*)eiv;
                s = __ldg(&ei[e]); d = __ldg(&ei[E + e]);
            } else {
                const int* ei = (const int*)eiv;
                s = __ldg(&ei[e]); d = __ldg(&ei[E + e]);
            }
            float4 v = __ldg(((const float4*)(x + s * 128)) + lane);
            float* dp = g_H + d * 128 + (lane << 2);
            asm volatile("red.global.add.v4.f32 [%0], {%1,%2,%3,%4};"
                         :: "l"(dp), "f"(v.x), "f"(v.y), "f"(v.z), "f"(v.w) : "memory");
        }
    }
}

// ============================ tf32 mma.sync GEMM ============================
// Z[m][n] = bias[n] + sum_k f(A[m][k]) * W[n][k]
// MODE 0: A=g_H,  f=identity,             Z=g_Z1
// MODE 1: A=g_Z1, f=relu(bn1(.)) (fused), Z=Zout
// Block: 128x128 tile, K=128 in smem (stride 132, conflict-free frags).
// 512 threads = 16 warps in 4(m) x 4(n); warp tile 32x32; mma.m16n8k8.tf32.
// Register double-buffered fragments; column sum/sumsq fused in epilogue.
#define MMA_SMEM_FLOATS (640 + 2 * 128 * 132)
#define MMA_SMEM_BYTES  (MMA_SMEM_FLOATS * 4)

__device__ __forceinline__ void mma_tf32_16n8k8(float c[4], const uint32_t a[4],
                                                uint32_t b0, uint32_t b1) {
    asm volatile(
        "mma.sync.aligned.m16n8k8.row.col.f32.tf32.tf32.f32 "
        "{%0,%1,%2,%3}, {%4,%5,%6,%7}, {%8,%9}, {%0,%1,%2,%3};"
        : "+f"(c[0]), "+f"(c[1]), "+f"(c[2]), "+f"(c[3])
        : "r"(a[0]), "r"(a[1]), "r"(a[2]), "r"(a[3]), "r"(b0), "r"(b1));
}

template <int MODE>
__global__ void __launch_bounds__(512) mma_gemm(const float* __restrict__ Wmat,
                                                const float* __restrict__ bias,
                                                float* __restrict__ Zout, int M) {
    extern __shared__ float sm[];
    float* s_bias  = sm;
    float* s_scale = sm + 128;
    float* s_shift = sm + 256;
    float* s_sum   = sm + 384;
    float* s_sq    = sm + 512;
    float* As      = sm + 640;             // [128][132] (tf32 bits)
    float* Bs      = As + 128 * 132;       // [128][132] (tf32 bits), [n][k]
    const uint32_t* As32 = (const uint32_t*)As;
    const uint32_t* Bs32 = (const uint32_t*)Bs;

    const float* A = MODE ? g_Z1 : g_H;
    float* Z       = MODE ? Zout : g_Z1;

    int tid = threadIdx.x;
    int m0 = blockIdx.x * 128;

    if (tid < 128) {
        s_bias[tid] = bias[tid];
        s_sum[tid] = 0.f;
        s_sq[tid]  = 0.f;
        if (MODE) { s_scale[tid] = g_bn[tid]; s_shift[tid] = g_bn[128 + tid]; }
    }
    __syncthreads();

    // load B (=W, [n][k] natural layout), tf32-rounded (4096 float4)
#pragma unroll
    for (int i = 0; i < 8; i++) {
        int idx = i * 512 + tid;
        int n = idx >> 5, k4 = idx & 31;
        float4 v = __ldg(((const float4*)Wmat) + idx);
        uint32_t* dst = (uint32_t*)(Bs + n * 132 + k4 * 4);
        dst[0] = to_tf32(v.x); dst[1] = to_tf32(v.y);
        dst[2] = to_tf32(v.z); dst[3] = to_tf32(v.w);
    }
    // load A tile (fused bn1+relu in MODE 1), tf32-rounded
#pragma unroll
    for (int i = 0; i < 8; i++) {
        int idx = i * 512 + tid;
        int m = idx >> 5, k4 = idx & 31;
        int gm = m0 + m;
        float4 v = make_float4(0.f, 0.f, 0.f, 0.f);
        if (gm < M) v = __ldg(((const float4*)A) + (size_t)gm * 32 + k4);
        if (MODE) {
            int k = k4 * 4;
            v.x = fmaxf(fmaf(v.x, s_scale[k + 0], s_shift[k + 0]), 0.f);
            v.y = fmaxf(fmaf(v.y, s_scale[k + 1], s_shift[k + 1]), 0.f);
            v.z = fmaxf(fmaf(v.z, s_scale[k + 2], s_shift[k + 2]), 0.f);
            v.w = fmaxf(fmaf(v.w, s_scale[k + 3], s_shift[k + 3]), 0.f);
        }
        uint32_t* dst = (uint32_t*)(As + m * 132 + k4 * 4);
        dst[0] = to_tf32(v.x); dst[1] = to_tf32(v.y);
        dst[2] = to_tf32(v.z); dst[3] = to_tf32(v.w);
    }
    __syncthreads();

    int lane = tid & 31;
    int wid  = tid >> 5;                   // 0..15
    int g = lane >> 2, t = lane & 3;
    int wm = wid >> 2;                     // 0..3
    int wn = wid & 3;                      // 0..3
    int arow = wm * 32;                    // warp's A row base (in tile)
    int bcol = wn * 32;                    // warp's B col base (in tile)

    float acc[2][4][4];
#pragma unroll
    for (int mt = 0; mt < 2; mt++)
#pragma unroll
        for (int nt = 0; nt < 4; nt++)
#pragma unroll
            for (int q = 0; q < 4; q++) acc[mt][nt][q] = 0.f;

    // double-buffered fragments
    uint32_t a[2][2][4];
    uint32_t b[2][4][2];

#define LOAD_FRAG(ks, buf)                                                   \
    do {                                                                     \
        int _k0 = (ks) * 8;                                                  \
        _Pragma("unroll")                                                    \
        for (int mt = 0; mt < 2; mt++) {                                     \
            int rb = arow + mt * 16;                                         \
            a[buf][mt][0] = As32[(rb + g) * 132 + _k0 + t];                  \
            a[buf][mt][1] = As32[(rb + g + 8) * 132 + _k0 + t];              \
            a[buf][mt][2] = As32[(rb + g) * 132 + _k0 + t + 4];              \
            a[buf][mt][3] = As32[(rb + g + 8) * 132 + _k0 + t + 4];          \
        }                                                                    \
        _Pragma("unroll")                                                    \
        for (int nt = 0; nt < 4; nt++) {                                     \
            b[buf][nt][0] = Bs32[(bcol + nt * 8 + g) * 132 + _k0 + t];       \
            b[buf][nt][1] = Bs32[(bcol + nt * 8 + g) * 132 + _k0 + t + 4];   \
        }                                                                    \
    } while (0)

    LOAD_FRAG(0, 0);
#pragma unroll
    for (int ks = 0; ks < 16; ks++) {
        int cur = ks & 1;
        if (ks < 15) LOAD_FRAG(ks + 1, cur ^ 1);
#pragma unroll
        for (int nt = 0; nt < 4; nt++) {
            mma_tf32_16n8k8(acc[0][nt], a[cur][0], b[cur][nt][0], b[cur][nt][1]);
            mma_tf32_16n8k8(acc[1][nt], a[cur][1], b[cur][nt][0], b[cur][nt][1]);
        }
    }
#undef LOAD_FRAG

    // epilogue: bias add, store float2 pairs, fused column stats
#pragma unroll
    for (int nt = 0; nt < 4; nt++) {
        int col = bcol + nt * 8 + 2 * t;
        float bi0 = s_bias[col], bi1 = s_bias[col + 1];
        float cs0 = 0.f, cq0 = 0.f, cs1 = 0.f, cq1 = 0.f;
#pragma unroll
        for (int mt = 0; mt < 2; mt++) {
#pragma unroll
            for (int rr = 0; rr < 2; rr++) {
                int gm = m0 + arow + mt * 16 + g + rr * 8;
                if (gm < M) {
                    float o0 = acc[mt][nt][rr * 2 + 0] + bi0;
                    float o1 = acc[mt][nt][rr * 2 + 1] + bi1;
                    float2 ov = make_float2(o0, o1);
                    *(float2*)(Z + (size_t)gm * 128 + col) = ov;
                    cs0 += o0; cq0 += o0 * o0;
                    cs1 += o1; cq1 += o1 * o1;
                }
            }
        }
        atomicAdd(&s_sum[col], cs0);     atomicAdd(&s_sq[col], cq0);
        atomicAdd(&s_sum[col + 1], cs1); atomicAdd(&s_sq[col + 1], cq1);
    }
    __syncthreads();
    if (tid < 128) {
        double* sum = g_stats + (MODE ? 256 : 0);
        double* sq  = g_stats + (MODE ? 384 : 128);
        atomicAdd(&sum[tid], (double)s_sum[tid]);
        atomicAdd(&sq[tid],  (double)s_sq[tid]);
    }
}

// ---- fold BN (mean/var/gamma/beta) into per-column scale/shift ----
template <int MODE>
__global__ void finalize_bn(const float* __restrict__ gamma,
                            const float* __restrict__ beta, int M) {
    int c = threadIdx.x;
    const double* sum = g_stats + (MODE ? 256 : 0);
    const double* sq  = g_stats + (MODE ? 384 : 128);
    double mean = sum[c] / (double)M;
    double var  = sq[c] / (double)M - mean * mean;
    float sc = gamma[c] * rsqrtf((float)var + 1e-5f);
    g_bn[MODE * 256 + c]       = sc;
    g_bn[MODE * 256 + 128 + c] = beta[c] - (float)mean * sc;
}

// ---- final: out = relu(bn2(out)) in place ----
__global__ void bn_relu_out_kernel(float* __restrict__ out, int n4) {
    int idx = blockIdx.x * blockDim.x + threadIdx.x;
    if (idx >= n4) return;
    float4 v = ((float4*)out)[idx];
    int k = (idx & 31) * 4;
    v.x = fmaxf(fmaf(v.x, g_bn[256 + k + 0], g_bn[384 + k + 0]), 0.f);
    v.y = fmaxf(fmaf(v.y, g_bn[256 + k + 1], g_bn[384 + k + 1]), 0.f);
    v.z = fmaxf(fmaf(v.z, g_bn[256 + k + 2], g_bn[384 + k + 2]), 0.f);
    v.w = fmaxf(fmaf(v.w, g_bn[256 + k + 3], g_bn[384 + k + 3]), 0.f);
    ((float4*)out)[idx] = v;
}

extern "C" void kernel_launch(void* const* d_in, const int* in_sizes, int n_in,
                              void* d_out, int out_size) {
    const float* x   = (const float*)d_in[0];
    const void*  ei  = d_in[1];
    // d_in[2] = batch (unused; single graph, BN over all nodes)
    const float* eps = (const float*)d_in[3];
    const float* W1  = (const float*)d_in[4];
    const float* b1  = (const float*)d_in[5];
    const float* g1  = (const float*)d_in[6];
    const float* be1 = (const float*)d_in[7];
    const float* W2  = (const float*)d_in[8];
    const float* b2  = (const float*)d_in[9];
    const float* g2  = (const float*)d_in[10];
    const float* be2 = (const float*)d_in[11];
    float* out = (float*)d_out;

    int N = in_sizes[0] / 128;
    int E = in_sizes[1] / 2;
    int n4 = N * 32;

    cudaFuncSetAttribute(mma_gemm<0>, cudaFuncAttributeMaxDynamicSharedMemorySize, MMA_SMEM_BYTES);
    cudaFuncSetAttribute(mma_gemm<1>, cudaFuncAttributeMaxDynamicSharedMemorySize, MMA_SMEM_BYTES);

    prep_kernel<<<1, 512>>>(ei, E, N);
    init_h_kernel<<<(n4 + 255) / 256, 256>>>(x, eps, n4);
    // 8 edges per warp -> 64 edges per 256-thread block
    scatter_kernel<<<(E + 63) / 64, 256>>>(x, ei, E);

    int gblocks = (N + 127) / 128;
    mma_gemm<0><<<gblocks, 512, MMA_SMEM_BYTES>>>(W1, b1, nullptr, N);
    finalize_bn<0><<<1, 128>>>(g1, be1, N);

    mma_gemm<1><<<gblocks, 512, MMA_SMEM_BYTES>>>(W2, b2, out, N);
    finalize_bn<1><<<1, 128>>>(g2, be2, N);

    bn_relu_out_kernel<<<(n4 + 255) / 256, 256>>>(out, n4);
}